// round 12
// baseline (speedup 1.0000x reference)
#include <cuda_runtime.h>
#include <cuda_fp16.h>
#include <cstdint>

// Problem dims
#define GM 512      // batch
#define GK 4096     // IN
#define GN 11008    // OUT

// Chunked overlap: K split into 4 chunks of 1024
#define KCHUNK   1024
#define NCHUNK   (GK / KCHUNK)    // 4

// GEMM tiling (R9 best config): BM=128, BN=128, BK=64, 3-stage, occ 2
#define BM      128
#define BN      128
#define BK      64
#define KSUB    2                 // split-k within a chunk
#define KDEPTH  (KCHUNK / KSUB)   // 512
#define NKT     (KDEPTH / BK)     // 8 k-tiles per consumer CTA
#define NCONS   ((GN / BN) * (GM / BM) * KSUB)   // 86*4*2 = 688
#define NPROD   128
#define THREADS 256
#define PAD     8
#define LDS_K   (BK + PAD)        // 72 halves -> 144B rows, ldmatrix conflict-free
#define STAGES  3

// Scratch (allocation-free rule: __device__ globals)
__device__ __half g_w[(size_t)GN * GK];   // 90MB decompressed fp16 W (L2-warm per chunk)
__device__ __half g_x[(size_t)GM * GK];   // 4MB fp16 x

// ---------------------------------------------------------------------------
__device__ __forceinline__ uint32_t smem_u32(const void* p) {
    return (uint32_t)__cvta_generic_to_shared(p);
}
__device__ __forceinline__ void cp_async16(void* smem, const void* gmem) {
    asm volatile("cp.async.cg.shared.global [%0], [%1], 16;\n"
                 ::"r"(smem_u32(smem)), "l"(gmem));
}

// ---------------------------------------------------------------------------
// Decompress one k-chunk of W (QINS LUT + sign-bit XOR), grid-stride.
// ---------------------------------------------------------------------------
__device__ __forceinline__ void decompress_chunk_body(
    const int* __restrict__ stored, const int* __restrict__ sign,
    const unsigned short* lut, int chunk, long long start, long long stride) {
    const long long n8c = (long long)GN * KCHUNK / 8;   // 1,409,024
#pragma unroll 2
    for (long long i = start; i < n8c; i += stride) {
        long long w = i * 8;
        int r = (int)(w >> 10);          // row (out channel)
        int c = (int)(w & 1023);         // col within chunk
        size_t el = (size_t)r * GK + (size_t)chunk * KCHUNK + c;
        const int4* sp = (const int4*)(stored + el);
        const int4* gp = (const int4*)(sign + el);
        int4 sa = sp[0], sb = sp[1];
        int4 ga = gp[0], gb = gp[1];
        unsigned int h0 = lut[sa.x] ^ ((((unsigned)ga.x) >> 16) & 0x8000u);
        unsigned int h1 = lut[sa.y] ^ ((((unsigned)ga.y) >> 16) & 0x8000u);
        unsigned int h2 = lut[sa.z] ^ ((((unsigned)ga.z) >> 16) & 0x8000u);
        unsigned int h3 = lut[sa.w] ^ ((((unsigned)ga.w) >> 16) & 0x8000u);
        unsigned int h4 = lut[sb.x] ^ ((((unsigned)gb.x) >> 16) & 0x8000u);
        unsigned int h5 = lut[sb.y] ^ ((((unsigned)gb.y) >> 16) & 0x8000u);
        unsigned int h6 = lut[sb.z] ^ ((((unsigned)gb.z) >> 16) & 0x8000u);
        unsigned int h7 = lut[sb.w] ^ ((((unsigned)gb.w) >> 16) & 0x8000u);
        uint4 o;
        o.x = h0 | (h1 << 16);
        o.y = h2 | (h3 << 16);
        o.z = h4 | (h5 << 16);
        o.w = h6 | (h7 << 16);
        *(uint4*)(g_w + el) = o;
    }
}

__device__ __forceinline__ void build_lut(unsigned short* lut, int tid,
                                          const float* lmin_p, const float* lmax_p) {
    float lmin = *lmin_p;
    float lrange = *lmax_p - lmin;
    for (int i = tid; i < 256; i += THREADS) {
        float lw = lmin + ((255.0f - (float)i) * (1.0f / 254.0f)) * lrange;
        lut[i] = __half_as_ushort(__float2half_rn(__expf(lw)));
    }
}

// Standalone chunk decompress (first pipeline step; high occupancy, no big smem)
__global__ void k_decompress_chunk(const int* __restrict__ stored,
                                   const int* __restrict__ sign,
                                   const float* __restrict__ lmin_p,
                                   const float* __restrict__ lmax_p, int chunk) {
    __shared__ unsigned short lut[256];
    build_lut(lut, threadIdx.x, lmin_p, lmax_p);
    __syncthreads();
    decompress_chunk_body(stored, sign, lut, chunk,
                          (long long)blockIdx.x * THREADS + threadIdx.x,
                          (long long)gridDim.x * THREADS);
}

// ---------------------------------------------------------------------------
__global__ void k_convert_x(const float* __restrict__ x) {
    const int n4 = GM * GK / 4;
    uint2* xo = (uint2*)g_x;
    const float4* xi = (const float4*)x;
    for (int i = blockIdx.x * blockDim.x + threadIdx.x; i < n4;
         i += gridDim.x * blockDim.x) {
        float4 v = xi[i];
        __half2 a = __floats2half2_rn(v.x, v.y);
        __half2 b = __floats2half2_rn(v.z, v.w);
        uint2 o;
        o.x = *(unsigned int*)&a;
        o.y = *(unsigned int*)&b;
        xo[i] = o;
    }
}

// out[b][o] = bias[o]*scale[o]; chunked GEMM partials (scaled) red.add on top
__global__ void k_init_out(const float* __restrict__ bias,
                           const float* __restrict__ scale,
                           float* __restrict__ out) {
    const int n4 = GM * GN / 4;
    const int gn4 = GN / 4;
    float4* o4 = (float4*)out;
    const float4* b4 = (const float4*)bias;
    const float4* s4 = (const float4*)scale;
    for (int i = blockIdx.x * blockDim.x + threadIdx.x; i < n4;
         i += gridDim.x * blockDim.x) {
        int c = i % gn4;
        float4 b = b4[c];
        float4 s = s4[c];
        float4 r;
        r.x = b.x * s.x; r.y = b.y * s.y; r.z = b.z * s.z; r.w = b.w * s.w;
        o4[i] = r;
    }
}

// ---------------------------------------------------------------------------
// Merged pipeline step: CTAs [0, ncons) run the R9 GEMM on chunk_g;
// CTAs [ncons, ncons+NPROD) decompress chunk_d (next chunk) concurrently.
// No intra-launch dependency: G reads only W written by PREVIOUS launches.
// ---------------------------------------------------------------------------
#define SMEM_DYN (STAGES * (BM + BN) * LDS_K * 2)   // 110592 B

__global__ void __launch_bounds__(THREADS, 2)
k_merged(const int* __restrict__ stored, const int* __restrict__ sign,
         const float* __restrict__ lmin_p, const float* __restrict__ lmax_p,
         const float* __restrict__ scale, float* __restrict__ out,
         int chunk_d, int chunk_g, int ncons) {
    extern __shared__ __half dynsmem[];
    const int tid = threadIdx.x;

    if ((int)blockIdx.x >= ncons) {
        // ---------------- producer: decompress chunk_d ----------------
        __shared__ unsigned short lut[256];
        build_lut(lut, tid, lmin_p, lmax_p);
        __syncthreads();
        int pid = blockIdx.x - ncons;
        decompress_chunk_body(stored, sign, lut, chunk_d,
                              (long long)pid * THREADS + tid,
                              (long long)NPROD * THREADS);
        return;
    }

    // ---------------- consumer: GEMM on chunk_g (R9 config) ----------------
    const int lane = tid & 31;
    const int warp = tid >> 5;
    const int wm = warp & 1;    // 0..1 over M
    const int wn = warp >> 1;   // 0..3 over N
    int idx = blockIdx.x;
    const int nt = idx % (GN / BN);
    idx /= (GN / BN);
    const int mt = idx % (GM / BM);
    const int kz = idx / (GM / BM);
    const int n0 = nt * BN;
    const int m0 = mt * BM;
    const int kbase = chunk_g * KCHUNK + kz * KDEPTH;

    float acc[4][4][4];
#pragma unroll
    for (int a = 0; a < 4; a++)
#pragma unroll
        for (int b = 0; b < 4; b++)
#pragma unroll
            for (int c = 0; c < 4; c++) acc[a][b][c] = 0.f;

    auto load_stage = [&](int st, int kt) {
        __half* base = dynsmem + st * (BM + BN) * LDS_K;
        __half* Asm = base;
        __half* Wsm = base + BM * LDS_K;
        const int kk = kbase + kt * BK;
#pragma unroll
        for (int j = 0; j < 4; ++j) {
            int t = tid + j * THREADS;     // 0..1023
            int row = t >> 3;              // 0..127
            int cx = t & 7;
            cp_async16(Asm + row * LDS_K + cx * 8,
                       g_x + (size_t)(m0 + row) * GK + kk + cx * 8);
            cp_async16(Wsm + row * LDS_K + cx * 8,
                       g_w + (size_t)(n0 + row) * GK + kk + cx * 8);
        }
    };

    load_stage(0, 0);
    asm volatile("cp.async.commit_group;\n" ::: "memory");
    load_stage(1, 1);
    asm volatile("cp.async.commit_group;\n" ::: "memory");

    const int arow = lane & 15;
    const int acol = (lane >> 4) * 8;

    for (int kt = 0; kt < NKT; ++kt) {
        const int st = kt % STAGES;
        asm volatile("cp.async.wait_group 1;\n" ::: "memory");
        __syncthreads();

        if (kt + 2 < NKT) load_stage((kt + 2) % STAGES, kt + 2);
        asm volatile("cp.async.commit_group;\n" ::: "memory");

        __half* base = dynsmem + st * (BM + BN) * LDS_K;
        __half* Asm = base;
        __half* Wsm = base + BM * LDS_K;

#pragma unroll
        for (int ks = 0; ks < BK / 16; ++ks) {
            unsigned int afr[4][4];
            unsigned int bfr[4][2];
#pragma unroll
            for (int mi = 0; mi < 4; ++mi) {
                unsigned int addr = smem_u32(
                    Asm + (wm * 64 + mi * 16 + arow) * LDS_K + ks * 16 + acol);
                asm volatile(
                    "ldmatrix.sync.aligned.m8n8.x4.shared.b16 {%0,%1,%2,%3}, [%4];\n"
                    : "=r"(afr[mi][0]), "=r"(afr[mi][1]), "=r"(afr[mi][2]),
                      "=r"(afr[mi][3])
                    : "r"(addr));
            }
#pragma unroll
            for (int nj = 0; nj < 2; ++nj) {
                unsigned int q0, q1, q2, q3;
                unsigned int addr = smem_u32(
                    Wsm + (wn * 32 + nj * 16 + arow) * LDS_K + ks * 16 + acol);
                asm volatile(
                    "ldmatrix.sync.aligned.m8n8.x4.shared.b16 {%0,%1,%2,%3}, [%4];\n"
                    : "=r"(q0), "=r"(q1), "=r"(q2), "=r"(q3)
                    : "r"(addr));
                bfr[nj * 2][0] = q0;
                bfr[nj * 2][1] = q2;
                bfr[nj * 2 + 1][0] = q1;
                bfr[nj * 2 + 1][1] = q3;
            }
#pragma unroll
            for (int mi = 0; mi < 4; ++mi)
#pragma unroll
                for (int nf = 0; nf < 4; ++nf) {
                    asm volatile(
                        "mma.sync.aligned.m16n8k16.row.col.f32.f16.f16.f32 "
                        "{%0,%1,%2,%3}, {%4,%5,%6,%7}, {%8,%9}, {%0,%1,%2,%3};\n"
                        : "+f"(acc[mi][nf][0]), "+f"(acc[mi][nf][1]),
                          "+f"(acc[mi][nf][2]), "+f"(acc[mi][nf][3])
                        : "r"(afr[mi][0]), "r"(afr[mi][1]), "r"(afr[mi][2]),
                          "r"(afr[mi][3]), "r"(bfr[nf][0]), "r"(bfr[nf][1]));
                }
        }
    }

    // epilogue: atomicAdd(out, scale*acc); out pre-initialized with bias*scale
    const int row = lane >> 2;
    const int col2 = (lane & 3) * 2;
#pragma unroll
    for (int mi = 0; mi < 4; ++mi) {
        int m = m0 + wm * 64 + mi * 16 + row;
#pragma unroll
        for (int nf = 0; nf < 4; ++nf) {
            int nn = n0 + wn * 32 + nf * 8 + col2;
            float s0 = scale[nn], s1 = scale[nn + 1];
            atomicAdd(&out[(size_t)m * GN + nn],           acc[mi][nf][0] * s0);
            atomicAdd(&out[(size_t)m * GN + nn + 1],       acc[mi][nf][1] * s1);
            atomicAdd(&out[(size_t)(m + 8) * GN + nn],     acc[mi][nf][2] * s0);
            atomicAdd(&out[(size_t)(m + 8) * GN + nn + 1], acc[mi][nf][3] * s1);
        }
    }
}

// ---------------------------------------------------------------------------
extern "C" void kernel_launch(void* const* d_in, const int* in_sizes, int n_in,
                              void* d_out, int out_size) {
    const float* x      = (const float*)d_in[0];
    const int*   stored = (const int*)d_in[1];
    const int*   sign   = (const int*)d_in[2];
    const float* lmin   = (const float*)d_in[3];
    const float* lmax   = (const float*)d_in[4];
    const float* scale  = (const float*)d_in[5];
    const float* bias   = (const float*)d_in[6];
    float* out = (float*)d_out;

    cudaFuncSetAttribute(k_merged, cudaFuncAttributeMaxDynamicSharedMemorySize, SMEM_DYN);

    k_convert_x<<<512, 256>>>(x);
    k_init_out<<<1024, 256>>>(bias, scale, out);
    // pipeline: D(c0); [D(c1)|G(c0)]; [D(c2)|G(c1)]; [D(c3)|G(c2)]; G(c3)
    k_decompress_chunk<<<740, 256>>>(stored, sign, lmin, lmax, 0);
    for (int c = 0; c < NCHUNK; ++c) {
        int chunk_d = (c + 1 < NCHUNK) ? c + 1 : -1;
        int grid = NCONS + ((chunk_d >= 0) ? NPROD : 0);
        k_merged<<<grid, THREADS, SMEM_DYN>>>(stored, sign, lmin, lmax,
                                              scale, out, chunk_d, c, NCONS);
    }
}

// round 13
// speedup vs baseline: 1.1291x; 1.1291x over previous
#include <cuda_runtime.h>
#include <cuda_fp16.h>
#include <cstdint>

// Problem dims
#define GM 512      // batch
#define GK 4096     // IN
#define GN 11008    // OUT

// GEMM tiling: BM=128, BN=64, BK=64, 2-stage, split-K 2, occ 3 (more warps/SM)
#define BM      128
#define BN      64
#define BK      64
#define KSPLIT  2
#define KRANGE  (GK / KSPLIT)     // 2048
#define NK      (KRANGE / BK)     // 32 k-tiles per CTA
#define THREADS 256
#define PAD     8
#define LDS_K   (BK + PAD)        // 72 halves -> 144B rows, ldmatrix conflict-free
#define STAGES  2

// Scratch (allocation-free rule: __device__ globals)
__device__ __half g_w[(size_t)GN * GK];   // 90MB decompressed fp16 W (L2-resident)
__device__ __half g_x[(size_t)GM * GK];   // 4MB fp16 x

// ---------------------------------------------------------------------------
__device__ __forceinline__ uint32_t smem_u32(const void* p) {
    return (uint32_t)__cvta_generic_to_shared(p);
}
__device__ __forceinline__ void cp_async16(void* smem, const void* gmem) {
    asm volatile("cp.async.cg.shared.global [%0], [%1], 16;\n"
                 ::"r"(smem_u32(smem)), "l"(gmem));
}

// ---------------------------------------------------------------------------
// QINS decompress: 256-entry LUT, sign via fp16 sign-bit XOR. At DRAM roofline.
// ---------------------------------------------------------------------------
__global__ void k_decompress(const int* __restrict__ stored,
                             const int* __restrict__ sign,
                             const float* __restrict__ lmin_p,
                             const float* __restrict__ lmax_p) {
    __shared__ unsigned short lut[256];
    float lmin = *lmin_p;
    float lrange = *lmax_p - lmin;
    for (int i = threadIdx.x; i < 256; i += blockDim.x) {
        float lw = lmin + ((255.0f - (float)i) * (1.0f / 254.0f)) * lrange;
        lut[i] = __half_as_ushort(__float2half_rn(__expf(lw)));
    }
    __syncthreads();

    const int4* s4 = (const int4*)stored;
    const int4* g4 = (const int4*)sign;
    uint4* w4 = (uint4*)g_w;

    const long long n8 = (long long)GN * GK / 8;
    long long i = (long long)blockIdx.x * blockDim.x + threadIdx.x;
    const long long stride = (long long)gridDim.x * blockDim.x;

    for (; i < n8; i += stride) {
        int4 sa = s4[2 * i], sb = s4[2 * i + 1];
        int4 ga = g4[2 * i], gb = g4[2 * i + 1];
        unsigned int h0 = lut[sa.x] ^ ((((unsigned)ga.x) >> 16) & 0x8000u);
        unsigned int h1 = lut[sa.y] ^ ((((unsigned)ga.y) >> 16) & 0x8000u);
        unsigned int h2 = lut[sa.z] ^ ((((unsigned)ga.z) >> 16) & 0x8000u);
        unsigned int h3 = lut[sa.w] ^ ((((unsigned)ga.w) >> 16) & 0x8000u);
        unsigned int h4 = lut[sb.x] ^ ((((unsigned)gb.x) >> 16) & 0x8000u);
        unsigned int h5 = lut[sb.y] ^ ((((unsigned)gb.y) >> 16) & 0x8000u);
        unsigned int h6 = lut[sb.z] ^ ((((unsigned)gb.z) >> 16) & 0x8000u);
        unsigned int h7 = lut[sb.w] ^ ((((unsigned)gb.w) >> 16) & 0x8000u);
        uint4 o;
        o.x = h0 | (h1 << 16);
        o.y = h2 | (h3 << 16);
        o.z = h4 | (h5 << 16);
        o.w = h6 | (h7 << 16);
        w4[i] = o;
    }
}

// ---------------------------------------------------------------------------
__global__ void k_convert_x(const float* __restrict__ x) {
    const int n4 = GM * GK / 4;
    uint2* xo = (uint2*)g_x;
    const float4* xi = (const float4*)x;
    for (int i = blockIdx.x * blockDim.x + threadIdx.x; i < n4;
         i += gridDim.x * blockDim.x) {
        float4 v = xi[i];
        __half2 a = __floats2half2_rn(v.x, v.y);
        __half2 b = __floats2half2_rn(v.z, v.w);
        uint2 o;
        o.x = *(unsigned int*)&a;
        o.y = *(unsigned int*)&b;
        xo[i] = o;
    }
}

// out[b][o] = bias[o]*scale[o]; split-K partials (scaled) red.add on top
__global__ void k_init_out(const float* __restrict__ bias,
                           const float* __restrict__ scale,
                           float* __restrict__ out) {
    const int n4 = GM * GN / 4;
    const int gn4 = GN / 4;
    float4* o4 = (float4*)out;
    const float4* b4 = (const float4*)bias;
    const float4* s4 = (const float4*)scale;
    for (int i = blockIdx.x * blockDim.x + threadIdx.x; i < n4;
         i += gridDim.x * blockDim.x) {
        int c = i % gn4;
        float4 b = b4[c];
        float4 s = s4[c];
        float4 r;
        r.x = b.x * s.x; r.y = b.y * s.y; r.z = b.z * s.z; r.w = b.w * s.w;
        o4[i] = r;
    }
}

// ---------------------------------------------------------------------------
// GEMM at occupancy 3: BM=128 x BN=64, 8 warps = 2(m) x 4(n), warp tile 64x16.
// 2-stage cp.async from g_w/g_x (L2-warm). Grid (172, 4, 2) = 1376 CTAs.
// Epilogue: atomicAdd(out, scale*acc); out pre-initialized with bias*scale.
// ---------------------------------------------------------------------------
#define SMEM_DYN (STAGES * (BM + BN) * LDS_K * 2)   // 55296 B -> 3 CTAs/SM

__global__ void __launch_bounds__(THREADS, 3)
k_gemm(const float* __restrict__ scale, float* __restrict__ out) {
    extern __shared__ __half dynsmem[];
    const int tid = threadIdx.x;
    const int lane = tid & 31;
    const int warp = tid >> 5;
    const int wm = warp & 1;    // 0..1 over M (64 rows each)
    const int wn = warp >> 1;   // 0..3 over N (16 cols each)
    const int n0 = blockIdx.x * BN;
    const int m0 = blockIdx.y * BM;
    const int kbase = blockIdx.z * KRANGE;

    float acc[4][2][4];
#pragma unroll
    for (int a = 0; a < 4; a++)
#pragma unroll
        for (int b = 0; b < 2; b++)
#pragma unroll
            for (int c = 0; c < 4; c++) acc[a][b][c] = 0.f;

    // per-stage: A 128x64 + W 64x64 halves = 1536 16B chunks -> 6/thread
    auto load_stage = [&](int st, int kt) {
        __half* base = dynsmem + st * (BM + BN) * LDS_K;
        __half* Asm = base;
        __half* Wsm = base + BM * LDS_K;
        const int kk = kbase + kt * BK;
#pragma unroll
        for (int j = 0; j < 4; ++j) {
            int t = tid + j * THREADS;     // 0..1023 over A chunks
            int row = t >> 3;              // 0..127
            int cx = t & 7;
            cp_async16(Asm + row * LDS_K + cx * 8,
                       g_x + (size_t)(m0 + row) * GK + kk + cx * 8);
        }
#pragma unroll
        for (int j = 0; j < 2; ++j) {
            int t = tid + j * THREADS;     // 0..511 over W chunks
            int row = t >> 3;              // 0..63
            int cx = t & 7;
            cp_async16(Wsm + row * LDS_K + cx * 8,
                       g_w + (size_t)(n0 + row) * GK + kk + cx * 8);
        }
    };

    load_stage(0, 0);
    asm volatile("cp.async.commit_group;\n" ::: "memory");
    load_stage(1, 1);
    asm volatile("cp.async.commit_group;\n" ::: "memory");

    const int arow = lane & 15;
    const int acol = (lane >> 4) * 8;

    for (int kt = 0; kt < NK; ++kt) {
        const int s = kt & 1;
        asm volatile("cp.async.wait_group 1;\n" ::: "memory");
        __syncthreads();   // stage s ready

        __half* base = dynsmem + s * (BM + BN) * LDS_K;
        __half* Asm = base;
        __half* Wsm = base + BM * LDS_K;

#pragma unroll
        for (int ks = 0; ks < BK / 16; ++ks) {
            unsigned int afr[4][4];
#pragma unroll
            for (int mi = 0; mi < 4; ++mi) {
                unsigned int addr = smem_u32(
                    Asm + (wm * 64 + mi * 16 + arow) * LDS_K + ks * 16 + acol);
                asm volatile(
                    "ldmatrix.sync.aligned.m8n8.x4.shared.b16 {%0,%1,%2,%3}, [%4];\n"
                    : "=r"(afr[mi][0]), "=r"(afr[mi][1]), "=r"(afr[mi][2]),
                      "=r"(afr[mi][3])
                    : "r"(addr));
            }
            unsigned int q0, q1, q2, q3;
            {
                unsigned int addr = smem_u32(
                    Wsm + (wn * 16 + arow) * LDS_K + ks * 16 + acol);
                asm volatile(
                    "ldmatrix.sync.aligned.m8n8.x4.shared.b16 {%0,%1,%2,%3}, [%4];\n"
                    : "=r"(q0), "=r"(q1), "=r"(q2), "=r"(q3)
                    : "r"(addr));
            }
#pragma unroll
            for (int mi = 0; mi < 4; ++mi) {
                asm volatile(
                    "mma.sync.aligned.m16n8k16.row.col.f32.f16.f16.f32 "
                    "{%0,%1,%2,%3}, {%4,%5,%6,%7}, {%8,%9}, {%0,%1,%2,%3};\n"
                    : "+f"(acc[mi][0][0]), "+f"(acc[mi][0][1]),
                      "+f"(acc[mi][0][2]), "+f"(acc[mi][0][3])
                    : "r"(afr[mi][0]), "r"(afr[mi][1]), "r"(afr[mi][2]),
                      "r"(afr[mi][3]), "r"(q0), "r"(q2));
                asm volatile(
                    "mma.sync.aligned.m16n8k16.row.col.f32.f16.f16.f32 "
                    "{%0,%1,%2,%3}, {%4,%5,%6,%7}, {%8,%9}, {%0,%1,%2,%3};\n"
                    : "+f"(acc[mi][1][0]), "+f"(acc[mi][1][1]),
                      "+f"(acc[mi][1][2]), "+f"(acc[mi][1][3])
                    : "r"(afr[mi][0]), "r"(afr[mi][1]), "r"(afr[mi][2]),
                      "r"(afr[mi][3]), "r"(q1), "r"(q3));
            }
        }

        __syncthreads();   // stage-s readers done before refill
        if (kt + 2 < NK) load_stage(s, kt + 2);
        asm volatile("cp.async.commit_group;\n" ::: "memory");
    }

    // epilogue: atomicAdd(out, scale*acc); out pre-initialized with bias*scale
    const int row = lane >> 2;
    const int col2 = (lane & 3) * 2;
#pragma unroll
    for (int mi = 0; mi < 4; ++mi) {
        int m = m0 + wm * 64 + mi * 16 + row;
#pragma unroll
        for (int nf = 0; nf < 2; ++nf) {
            int nn = n0 + wn * 16 + nf * 8 + col2;
            float s0 = scale[nn], s1 = scale[nn + 1];
            atomicAdd(&out[(size_t)m * GN + nn],           acc[mi][nf][0] * s0);
            atomicAdd(&out[(size_t)m * GN + nn + 1],       acc[mi][nf][1] * s1);
            atomicAdd(&out[(size_t)(m + 8) * GN + nn],     acc[mi][nf][2] * s0);
            atomicAdd(&out[(size_t)(m + 8) * GN + nn + 1], acc[mi][nf][3] * s1);
        }
    }
}

// ---------------------------------------------------------------------------
extern "C" void kernel_launch(void* const* d_in, const int* in_sizes, int n_in,
                              void* d_out, int out_size) {
    const float* x      = (const float*)d_in[0];
    const int*   stored = (const int*)d_in[1];
    const int*   sign   = (const int*)d_in[2];
    const float* lmin   = (const float*)d_in[3];
    const float* lmax   = (const float*)d_in[4];
    const float* scale  = (const float*)d_in[5];
    const float* bias   = (const float*)d_in[6];
    float* out = (float*)d_out;

    cudaFuncSetAttribute(k_gemm, cudaFuncAttributeMaxDynamicSharedMemorySize, SMEM_DYN);

    k_decompress<<<2960, 256>>>(stored, sign, lmin, lmax);
    k_convert_x<<<512, 256>>>(x);
    k_init_out<<<1024, 256>>>(bias, scale, out);
    dim3 grid(GN / BN, GM / BM, KSPLIT);   // (172, 4, 2)
    k_gemm<<<grid, THREADS, SMEM_DYN>>>(scale, out);
}

// round 14
// speedup vs baseline: 1.2190x; 1.0796x over previous
#include <cuda_runtime.h>
#include <cuda_fp16.h>
#include <cstdint>

// Problem dims
#define GM 512      // batch
#define GK 4096     // IN
#define GN 11008    // OUT

// GEMM tiling: BM=128, BN=128, BK=64, 3-stage, split-K 4, occ 2 (R9 + finer split)
#define BM      128
#define BN      128
#define BK      64
#define KSPLIT  4
#define KRANGE  (GK / KSPLIT)     // 1024
#define NK      (KRANGE / BK)     // 16 k-tiles per CTA
#define THREADS 256
#define PAD     8
#define LDS_K   (BK + PAD)        // 72 halves -> 144B rows, ldmatrix conflict-free
#define STAGES  3

// Scratch (allocation-free rule: __device__ globals)
__device__ __half g_w[(size_t)GN * GK];   // 90MB decompressed fp16 W (L2-resident)
__device__ __half g_x[(size_t)GM * GK];   // 4MB fp16 x

// ---------------------------------------------------------------------------
__device__ __forceinline__ uint32_t smem_u32(const void* p) {
    return (uint32_t)__cvta_generic_to_shared(p);
}
__device__ __forceinline__ void cp_async16(void* smem, const void* gmem) {
    asm volatile("cp.async.cg.shared.global [%0], [%1], 16;\n"
                 ::"r"(smem_u32(smem)), "l"(gmem));
}

// ---------------------------------------------------------------------------
// QINS decompress: 256-entry LUT, sign via fp16 sign-bit XOR. At DRAM roofline.
// ---------------------------------------------------------------------------
__global__ void k_decompress(const int* __restrict__ stored,
                             const int* __restrict__ sign,
                             const float* __restrict__ lmin_p,
                             const float* __restrict__ lmax_p) {
    __shared__ unsigned short lut[256];
    float lmin = *lmin_p;
    float lrange = *lmax_p - lmin;
    for (int i = threadIdx.x; i < 256; i += blockDim.x) {
        float lw = lmin + ((255.0f - (float)i) * (1.0f / 254.0f)) * lrange;
        lut[i] = __half_as_ushort(__float2half_rn(__expf(lw)));
    }
    __syncthreads();

    const int4* s4 = (const int4*)stored;
    const int4* g4 = (const int4*)sign;
    uint4* w4 = (uint4*)g_w;

    const long long n8 = (long long)GN * GK / 8;
    long long i = (long long)blockIdx.x * blockDim.x + threadIdx.x;
    const long long stride = (long long)gridDim.x * blockDim.x;

    for (; i < n8; i += stride) {
        int4 sa = s4[2 * i], sb = s4[2 * i + 1];
        int4 ga = g4[2 * i], gb = g4[2 * i + 1];
        unsigned int h0 = lut[sa.x] ^ ((((unsigned)ga.x) >> 16) & 0x8000u);
        unsigned int h1 = lut[sa.y] ^ ((((unsigned)ga.y) >> 16) & 0x8000u);
        unsigned int h2 = lut[sa.z] ^ ((((unsigned)ga.z) >> 16) & 0x8000u);
        unsigned int h3 = lut[sa.w] ^ ((((unsigned)ga.w) >> 16) & 0x8000u);
        unsigned int h4 = lut[sb.x] ^ ((((unsigned)gb.x) >> 16) & 0x8000u);
        unsigned int h5 = lut[sb.y] ^ ((((unsigned)gb.y) >> 16) & 0x8000u);
        unsigned int h6 = lut[sb.z] ^ ((((unsigned)gb.z) >> 16) & 0x8000u);
        unsigned int h7 = lut[sb.w] ^ ((((unsigned)gb.w) >> 16) & 0x8000u);
        uint4 o;
        o.x = h0 | (h1 << 16);
        o.y = h2 | (h3 << 16);
        o.z = h4 | (h5 << 16);
        o.w = h6 | (h7 << 16);
        w4[i] = o;
    }
}

// ---------------------------------------------------------------------------
// Merged prep: x fp32->fp16 AND out = bias*scale init, one launch.
// ---------------------------------------------------------------------------
__global__ void k_prep(const float* __restrict__ x,
                       const float* __restrict__ bias,
                       const float* __restrict__ scale,
                       float* __restrict__ out) {
    const int gstride = gridDim.x * blockDim.x;
    const int gid = blockIdx.x * blockDim.x + threadIdx.x;

    // x convert
    {
        const int n4 = GM * GK / 4;
        uint2* xo = (uint2*)g_x;
        const float4* xi = (const float4*)x;
        for (int i = gid; i < n4; i += gstride) {
            float4 v = xi[i];
            __half2 a = __floats2half2_rn(v.x, v.y);
            __half2 b = __floats2half2_rn(v.z, v.w);
            uint2 o;
            o.x = *(unsigned int*)&a;
            o.y = *(unsigned int*)&b;
            xo[i] = o;
        }
    }
    // out init
    {
        const int n4 = GM * GN / 4;
        const int gn4 = GN / 4;
        float4* o4 = (float4*)out;
        const float4* b4 = (const float4*)bias;
        const float4* s4 = (const float4*)scale;
        for (int i = gid; i < n4; i += gstride) {
            int c = i % gn4;
            float4 b = b4[c];
            float4 s = s4[c];
            float4 r;
            r.x = b.x * s.x; r.y = b.y * s.y; r.z = b.z * s.z; r.w = b.w * s.w;
            o4[i] = r;
        }
    }
}

// ---------------------------------------------------------------------------
// GEMM (R9 config, split-K 4): 3-stage cp.async from g_w/g_x (L2-warm).
// Grid (86, 4, 4) = 1376 CTAs. 8 warps = 2(m) x 4(n), warp tile 64x32.
// Prefetch issued after first ks block so MMAs start immediately post-barrier.
// Epilogue: atomicAdd(out, scale*acc); out pre-initialized with bias*scale.
// ---------------------------------------------------------------------------
#define SMEM_DYN (STAGES * (BM + BN) * LDS_K * 2)   // 110592 B

__global__ void __launch_bounds__(THREADS, 2)
k_gemm(const float* __restrict__ scale, float* __restrict__ out) {
    extern __shared__ __half dynsmem[];
    const int tid = threadIdx.x;
    const int lane = tid & 31;
    const int warp = tid >> 5;
    const int wm = warp & 1;    // 0..1 over M
    const int wn = warp >> 1;   // 0..3 over N
    const int n0 = blockIdx.x * BN;
    const int m0 = blockIdx.y * BM;
    const int kbase = blockIdx.z * KRANGE;

    float acc[4][4][4];
#pragma unroll
    for (int a = 0; a < 4; a++)
#pragma unroll
        for (int b = 0; b < 4; b++)
#pragma unroll
            for (int c = 0; c < 4; c++) acc[a][b][c] = 0.f;

    auto load_stage = [&](int st, int kt) {
        __half* base = dynsmem + st * (BM + BN) * LDS_K;
        __half* Asm = base;
        __half* Wsm = base + BM * LDS_K;
        const int kk = kbase + kt * BK;
#pragma unroll
        for (int j = 0; j < 4; ++j) {
            int t = tid + j * THREADS;     // 0..1023
            int row = t >> 3;              // 0..127
            int cx = t & 7;
            cp_async16(Asm + row * LDS_K + cx * 8,
                       g_x + (size_t)(m0 + row) * GK + kk + cx * 8);
            cp_async16(Wsm + row * LDS_K + cx * 8,
                       g_w + (size_t)(n0 + row) * GK + kk + cx * 8);
        }
    };

    load_stage(0, 0);
    asm volatile("cp.async.commit_group;\n" ::: "memory");
    load_stage(1, 1);
    asm volatile("cp.async.commit_group;\n" ::: "memory");

    const int arow = lane & 15;
    const int acol = (lane >> 4) * 8;

    for (int kt = 0; kt < NK; ++kt) {
        const int st = kt % STAGES;
        asm volatile("cp.async.wait_group 1;\n" ::: "memory");
        __syncthreads();   // stage st ready; all warps past compute of kt-1

        __half* base = dynsmem + st * (BM + BN) * LDS_K;
        __half* Asm = base;
        __half* Wsm = base + BM * LDS_K;

#pragma unroll
        for (int ks = 0; ks < BK / 16; ++ks) {
            unsigned int afr[4][4];
            unsigned int bfr[4][2];
#pragma unroll
            for (int mi = 0; mi < 4; ++mi) {
                unsigned int addr = smem_u32(
                    Asm + (wm * 64 + mi * 16 + arow) * LDS_K + ks * 16 + acol);
                asm volatile(
                    "ldmatrix.sync.aligned.m8n8.x4.shared.b16 {%0,%1,%2,%3}, [%4];\n"
                    : "=r"(afr[mi][0]), "=r"(afr[mi][1]), "=r"(afr[mi][2]),
                      "=r"(afr[mi][3])
                    : "r"(addr));
            }
#pragma unroll
            for (int nj = 0; nj < 2; ++nj) {
                unsigned int q0, q1, q2, q3;
                unsigned int addr = smem_u32(
                    Wsm + (wn * 32 + nj * 16 + arow) * LDS_K + ks * 16 + acol);
                asm volatile(
                    "ldmatrix.sync.aligned.m8n8.x4.shared.b16 {%0,%1,%2,%3}, [%4];\n"
                    : "=r"(q0), "=r"(q1), "=r"(q2), "=r"(q3)
                    : "r"(addr));
                bfr[nj * 2][0] = q0;
                bfr[nj * 2][1] = q2;
                bfr[nj * 2 + 1][0] = q1;
                bfr[nj * 2 + 1][1] = q3;
            }
#pragma unroll
            for (int mi = 0; mi < 4; ++mi)
#pragma unroll
                for (int nf = 0; nf < 4; ++nf) {
                    asm volatile(
                        "mma.sync.aligned.m16n8k16.row.col.f32.f16.f16.f32 "
                        "{%0,%1,%2,%3}, {%4,%5,%6,%7}, {%8,%9}, {%0,%1,%2,%3};\n"
                        : "+f"(acc[mi][nf][0]), "+f"(acc[mi][nf][1]),
                          "+f"(acc[mi][nf][2]), "+f"(acc[mi][nf][3])
                        : "r"(afr[mi][0]), "r"(afr[mi][1]), "r"(afr[mi][2]),
                          "r"(afr[mi][3]), "r"(bfr[nf][0]), "r"(bfr[nf][1]));
                }

            // after the first ks block, issue the prefetch for kt+2:
            // MMAs above start immediately post-barrier; LDG issue hides here
            if (ks == 0) {
                if (kt + 2 < NK) load_stage((kt + 2) % STAGES, kt + 2);
                asm volatile("cp.async.commit_group;\n" ::: "memory");
            }
        }
    }

    // epilogue: atomicAdd(out, scale*acc); out pre-initialized with bias*scale
    const int row = lane >> 2;
    const int col2 = (lane & 3) * 2;
#pragma unroll
    for (int mi = 0; mi < 4; ++mi) {
        int m = m0 + wm * 64 + mi * 16 + row;
#pragma unroll
        for (int nf = 0; nf < 4; ++nf) {
            int nn = n0 + wn * 32 + nf * 8 + col2;
            float s0 = scale[nn], s1 = scale[nn + 1];
            atomicAdd(&out[(size_t)m * GN + nn],           acc[mi][nf][0] * s0);
            atomicAdd(&out[(size_t)m * GN + nn + 1],       acc[mi][nf][1] * s1);
            atomicAdd(&out[(size_t)(m + 8) * GN + nn],     acc[mi][nf][2] * s0);
            atomicAdd(&out[(size_t)(m + 8) * GN + nn + 1], acc[mi][nf][3] * s1);
        }
    }
}

// ---------------------------------------------------------------------------
extern "C" void kernel_launch(void* const* d_in, const int* in_sizes, int n_in,
                              void* d_out, int out_size) {
    const float* x      = (const float*)d_in[0];
    const int*   stored = (const int*)d_in[1];
    const int*   sign   = (const int*)d_in[2];
    const float* lmin   = (const float*)d_in[3];
    const float* lmax   = (const float*)d_in[4];
    const float* scale  = (const float*)d_in[5];
    const float* bias   = (const float*)d_in[6];
    float* out = (float*)d_out;

    cudaFuncSetAttribute(k_gemm, cudaFuncAttributeMaxDynamicSharedMemorySize, SMEM_DYN);

    k_decompress<<<2960, 256>>>(stored, sign, lmin, lmax);
    k_prep<<<1024, 256>>>(x, bias, scale, out);
    dim3 grid(GN / BN, GM / BM, KSPLIT);   // (86, 4, 4)
    k_gemm<<<grid, THREADS, SMEM_DYN>>>(scale, out);
}